// round 1
// baseline (speedup 1.0000x reference)
#include <cuda_runtime.h>

#define NZ 64
#define NC 16
#define ND 64
#define N_PILLARS 65536
#define LN_EPS 1e-5f

// Scratch (device globals — no allocation allowed in kernel_launch)
__device__ float  g_zpart[NZ * ND];        // z_embed @ w_e + b1
__device__ float2 g_wpack[ND * 8];         // (w_v[2k][d], w_v[2k+1][d])

// ---------------------------------------------------------------------------
// f32x2 packed helpers (sm_100+)
// ---------------------------------------------------------------------------
__device__ __forceinline__ unsigned long long pack2(float a, float b) {
    unsigned long long r;
    asm("mov.b64 %0, {%1, %2};" : "=l"(r) : "f"(a), "f"(b));
    return r;
}
__device__ __forceinline__ void unpack2(unsigned long long v, float& a, float& b) {
    asm("mov.b64 {%0, %1}, %2;" : "=f"(a), "=f"(b) : "l"(v));
}
__device__ __forceinline__ void fma2(unsigned long long& d,
                                     unsigned long long a,
                                     unsigned long long b) {
    asm("fma.rn.f32x2 %0, %1, %2, %0;" : "+l"(d) : "l"(a), "l"(b));
}

// ---------------------------------------------------------------------------
// Prologue: z_part (64x64) and packed w_v
// ---------------------------------------------------------------------------
__global__ void prep_kernel(const float* __restrict__ z_embed,
                            const float* __restrict__ w1,
                            const float* __restrict__ b1) {
    int t = threadIdx.x;
    for (int i = t; i < NZ * ND; i += blockDim.x) {
        int z = i >> 6, d = i & 63;
        float s = b1[d];
#pragma unroll
        for (int c = 0; c < NC; c++)
            s += z_embed[z * NC + c] * w1[(NC + c) * ND + d];
        g_zpart[i] = s;
    }
    for (int i = t; i < ND * 8; i += blockDim.x) {
        int d = i >> 3, k = i & 7;
        g_wpack[i] = make_float2(w1[(2 * k) * ND + d], w1[(2 * k + 1) * ND + d]);
    }
}

// ---------------------------------------------------------------------------
// Main: 1 warp per pillar, 2 d-outputs per lane, packed-over-c f32x2 FMAs
// ---------------------------------------------------------------------------
__global__ __launch_bounds__(256, 4)
void bev_kernel(const float* __restrict__ vol,
                const float* __restrict__ gamma_,
                const float* __restrict__ beta_,
                float* __restrict__ out) {
    __shared__ float s_zpart[NZ * ND];
    int tid = threadIdx.x;
    for (int i = tid; i < NZ * ND; i += 256)
        s_zpart[i] = g_zpart[i];
    __syncthreads();

    int warp = tid >> 5, lane = tid & 31;
    int pillar = blockIdx.x * 8 + warp;
    int d0 = lane * 2;

    // Packed weights for this lane's two d-columns (loop invariant)
    unsigned long long wA[8], wB[8];
    {
        const float4* wp = (const float4*)g_wpack;  // [ND*4] float4
#pragma unroll
        for (int j = 0; j < 4; j++) {
            float4 a = wp[d0 * 4 + j];
            wA[2 * j]     = pack2(a.x, a.y);
            wA[2 * j + 1] = pack2(a.z, a.w);
            float4 b = wp[(d0 + 1) * 4 + j];
            wB[2 * j]     = pack2(b.x, b.y);
            wB[2 * j + 1] = pack2(b.z, b.w);
        }
    }

    const float4* vp = (const float4*)(vol + (size_t)pillar * (NZ * NC));
    float acc0 = 0.f, acc1 = 0.f;

#pragma unroll 4
    for (int z = 0; z < NZ; z++) {
        // 16 voxel features (uniform across the warp -> 4 broadcast LDG.128)
        float4 v0 = vp[z * 4 + 0];
        float4 v1 = vp[z * 4 + 1];
        float4 v2 = vp[z * 4 + 2];
        float4 v3 = vp[z * 4 + 3];
        unsigned long long p[8];
        p[0] = pack2(v0.x, v0.y); p[1] = pack2(v0.z, v0.w);
        p[2] = pack2(v1.x, v1.y); p[3] = pack2(v1.z, v1.w);
        p[4] = pack2(v2.x, v2.y); p[5] = pack2(v2.z, v2.w);
        p[6] = pack2(v3.x, v3.y); p[7] = pack2(v3.z, v3.w);

        unsigned long long s0 = 0ull, s1 = 0ull;
#pragma unroll
        for (int k = 0; k < 8; k++) {
            fma2(s0, p[k], wA[k]);
            fma2(s1, p[k], wB[k]);
        }
        float2 zp = *(const float2*)&s_zpart[z * ND + d0];
        float a, b;
        unpack2(s0, a, b);
        acc0 += fmaxf(a + b + zp.x, 0.f);
        unpack2(s1, a, b);
        acc1 += fmaxf(a + b + zp.y, 0.f);
    }

    // LayerNorm across the warp's 64 d-values (2 per lane)
    float s  = acc0 + acc1;
    float sq = acc0 * acc0 + acc1 * acc1;
#pragma unroll
    for (int o = 16; o; o >>= 1) {
        s  += __shfl_xor_sync(0xffffffffu, s,  o);
        sq += __shfl_xor_sync(0xffffffffu, sq, o);
    }
    float mean = s * (1.0f / 64.0f);
    float var  = sq * (1.0f / 64.0f) - mean * mean;
    float inv  = rsqrtf(var + LN_EPS);

    float2 g  = *(const float2*)&gamma_[d0];
    float2 be = *(const float2*)&beta_[d0];
    float2 o2;
    o2.x = (acc0 - mean) * inv * g.x + be.x;
    o2.y = (acc1 - mean) * inv * g.y + be.y;
    *(float2*)&out[(size_t)pillar * ND + d0] = o2;
}

// ---------------------------------------------------------------------------
// Launch
// ---------------------------------------------------------------------------
extern "C" void kernel_launch(void* const* d_in, const int* in_sizes, int n_in,
                              void* d_out, int out_size) {
    const float* vol     = (const float*)d_in[0];
    const float* z_embed = (const float*)d_in[1];
    const float* w1      = (const float*)d_in[2];
    const float* b1      = (const float*)d_in[3];
    const float* gamma_  = (const float*)d_in[4];
    const float* beta_   = (const float*)d_in[5];
    float* out = (float*)d_out;

    prep_kernel<<<1, 256>>>(z_embed, w1, b1);
    bev_kernel<<<N_PILLARS / 8, 256>>>(vol, gamma_, beta_, out);
}

// round 3
// speedup vs baseline: 1.6841x; 1.6841x over previous
#include <cuda_runtime.h>
#include <cstdint>

#define NZ 64
#define NC 16
#define ND 64
#define N_PILLARS 65536
#define LN_EPS 1e-5f

#define WARPS_PER_BLK 8
#define CHUNK_Z 16                       // z per staged chunk
#define NCHUNK (NZ / CHUNK_Z)            // 4
#define CHUNK_FLOATS (CHUNK_Z * NC)      // 256 floats = 1KB per pillar-chunk

// Scratch (device globals — no allocation allowed in kernel_launch)
__device__ float  g_zpart[NZ * ND];      // z_embed @ w_e + b1
__device__ float2 g_wpack[ND * 8];       // (w_v[2k][d], w_v[2k+1][d])

// ---------------------------------------------------------------------------
// f32x2 packed helpers (sm_100+)
// ---------------------------------------------------------------------------
__device__ __forceinline__ unsigned long long pack2(float a, float b) {
    unsigned long long r;
    asm("mov.b64 %0, {%1, %2};" : "=l"(r) : "f"(a), "f"(b));
    return r;
}
__device__ __forceinline__ void unpack2(unsigned long long v, float& a, float& b) {
    asm("mov.b64 {%0, %1}, %2;" : "=f"(a), "=f"(b) : "l"(v));
}
__device__ __forceinline__ void fma2(unsigned long long& d,
                                     unsigned long long a,
                                     unsigned long long b) {
    asm("fma.rn.f32x2 %0, %1, %2, %0;" : "+l"(d) : "l"(a), "l"(b));
}

// cp.async 16B global->shared
__device__ __forceinline__ void cp16(uint32_t smem_dst, const void* gsrc) {
    asm volatile("cp.async.cg.shared.global [%0], [%1], 16;\n"
                 :: "r"(smem_dst), "l"(gsrc) : "memory");
}
__device__ __forceinline__ void cp_commit() {
    asm volatile("cp.async.commit_group;\n" ::: "memory");
}
template <int N>
__device__ __forceinline__ void cp_wait() {
    asm volatile("cp.async.wait_group %0;\n" :: "n"(N) : "memory");
}

// ---------------------------------------------------------------------------
// Prologue: z_part (64x64) and packed w_v
// ---------------------------------------------------------------------------
__global__ void prep_kernel(const float* __restrict__ z_embed,
                            const float* __restrict__ w1,
                            const float* __restrict__ b1) {
    int t = threadIdx.x;
    for (int i = t; i < NZ * ND; i += blockDim.x) {
        int z = i >> 6, d = i & 63;
        float s = b1[d];
#pragma unroll
        for (int c = 0; c < NC; c++)
            s += z_embed[z * NC + c] * w1[(NC + c) * ND + d];
        g_zpart[i] = s;
    }
    for (int i = t; i < ND * 8; i += blockDim.x) {
        int d = i >> 3, k = i & 7;
        g_wpack[i] = make_float2(w1[(2 * k) * ND + d], w1[(2 * k + 1) * ND + d]);
    }
}

// ---------------------------------------------------------------------------
// Main: 1 warp per pillar; cp.async double-buffered staging; broadcast LDS
// ---------------------------------------------------------------------------
__global__ __launch_bounds__(256, 4)
void bev_kernel(const float* __restrict__ vol,
                const float* __restrict__ gamma_,
                const float* __restrict__ beta_,
                float* __restrict__ out) {
    __shared__ float s_zpart[NZ * ND];                                      // 16KB
    __shared__ __align__(16) float s_stage[2][WARPS_PER_BLK][CHUNK_FLOATS]; // 16KB

    int tid = threadIdx.x;
    for (int i = tid; i < NZ * ND; i += 256)
        s_zpart[i] = g_zpart[i];
    __syncthreads();

    int warp = tid >> 5, lane = tid & 31;
    int pillar = blockIdx.x * WARPS_PER_BLK + warp;
    int d0 = lane * 2;

    // Packed weights for this lane's two d-columns (loop invariant, 32 regs)
    unsigned long long wA[8], wB[8];
    {
        const float4* wp = (const float4*)g_wpack;  // [ND*4] float4
#pragma unroll
        for (int j = 0; j < 4; j++) {
            float4 a = wp[d0 * 4 + j];
            wA[2 * j]     = pack2(a.x, a.y);
            wA[2 * j + 1] = pack2(a.z, a.w);
            float4 b = wp[(d0 + 1) * 4 + j];
            wB[2 * j]     = pack2(b.x, b.y);
            wB[2 * j + 1] = pack2(b.z, b.w);
        }
    }

    const char* gbase = (const char*)(vol + (size_t)pillar * (NZ * NC));

    // smem byte address of this warp's stage buffers
    uint32_t stage_base[2];
    stage_base[0] = (uint32_t)__cvta_generic_to_shared(&s_stage[0][warp][0]);
    stage_base[1] = (uint32_t)__cvta_generic_to_shared(&s_stage[1][warp][0]);

    // issue one 1KB chunk: 2 x cp.async(16B) per lane, coalesced
    auto issue = [&](int buf, int chunk) {
        const char* src = gbase + chunk * 1024 + lane * 16;
        uint32_t dst = stage_base[buf] + lane * 16;
        cp16(dst, src);
        cp16(dst + 512, src + 512);
        cp_commit();
    };

    issue(0, 0);
    issue(1, 1);

    float acc0 = 0.f, acc1 = 0.f;

    for (int c = 0; c < NCHUNK; c++) {
        if (c == NCHUNK - 1) cp_wait<0>(); else cp_wait<1>();
        __syncwarp();

        const ulonglong2* sp = (const ulonglong2*)&s_stage[c & 1][warp][0];
#pragma unroll 4
        for (int zz = 0; zz < CHUNK_Z; zz++) {
            // 16 voxel floats = 8 packed f32x2, broadcast LDS.128 x4
            ulonglong2 q0 = sp[zz * 4 + 0];
            ulonglong2 q1 = sp[zz * 4 + 1];
            ulonglong2 q2 = sp[zz * 4 + 2];
            ulonglong2 q3 = sp[zz * 4 + 3];

            unsigned long long s0 = 0ull, s1 = 0ull;
            fma2(s0, q0.x, wA[0]); fma2(s1, q0.x, wB[0]);
            fma2(s0, q0.y, wA[1]); fma2(s1, q0.y, wB[1]);
            fma2(s0, q1.x, wA[2]); fma2(s1, q1.x, wB[2]);
            fma2(s0, q1.y, wA[3]); fma2(s1, q1.y, wB[3]);
            fma2(s0, q2.x, wA[4]); fma2(s1, q2.x, wB[4]);
            fma2(s0, q2.y, wA[5]); fma2(s1, q2.y, wB[5]);
            fma2(s0, q3.x, wA[6]); fma2(s1, q3.x, wB[6]);
            fma2(s0, q3.y, wA[7]); fma2(s1, q3.y, wB[7]);

            int z = c * CHUNK_Z + zz;
            float2 zp = *(const float2*)&s_zpart[z * ND + d0];
            float a, b;
            unpack2(s0, a, b);
            acc0 += fmaxf(a + b + zp.x, 0.f);
            unpack2(s1, a, b);
            acc1 += fmaxf(a + b + zp.y, 0.f);
        }
        __syncwarp();
        if (c + 2 < NCHUNK) issue(c & 1, c + 2);
    }

    // LayerNorm across the warp's 64 d-values (2 per lane)
    float s  = acc0 + acc1;
    float sq = acc0 * acc0 + acc1 * acc1;
#pragma unroll
    for (int o = 16; o; o >>= 1) {
        s  += __shfl_xor_sync(0xffffffffu, s,  o);
        sq += __shfl_xor_sync(0xffffffffu, sq, o);
    }
    float mean = s * (1.0f / 64.0f);
    float var  = sq * (1.0f / 64.0f) - mean * mean;
    float inv  = rsqrtf(var + LN_EPS);

    float2 g  = *(const float2*)&gamma_[d0];
    float2 be = *(const float2*)&beta_[d0];
    float2 o2;
    o2.x = (acc0 - mean) * inv * g.x + be.x;
    o2.y = (acc1 - mean) * inv * g.y + be.y;
    *(float2*)&out[(size_t)pillar * ND + d0] = o2;
}

// ---------------------------------------------------------------------------
// Launch
// ---------------------------------------------------------------------------
extern "C" void kernel_launch(void* const* d_in, const int* in_sizes, int n_in,
                              void* d_out, int out_size) {
    const float* vol     = (const float*)d_in[0];
    const float* z_embed = (const float*)d_in[1];
    const float* w1      = (const float*)d_in[2];
    const float* b1      = (const float*)d_in[3];
    const float* gamma_  = (const float*)d_in[4];
    const float* beta_   = (const float*)d_in[5];
    float* out = (float*)d_out;

    prep_kernel<<<1, 256>>>(z_embed, w1, b1);
    bev_kernel<<<N_PILLARS / WARPS_PER_BLK, 256>>>(vol, gamma_, beta_, out);
}

// round 5
// speedup vs baseline: 2.3125x; 1.3731x over previous
#include <cuda_runtime.h>
#include <cuda_bf16.h>
#include <cstdint>

#define NZ 64
#define NC 16
#define ND 64
#define NP 65536
#define LN_EPS 1e-5f

// Prepped constants
__device__ float    g_zpart[NZ * ND];    // exact fp32 z_embed@w_e + b1
__device__ uint32_t g_wpk_hi[8 * ND];    // [kpair][d] bf16x2 {lo: c=2kp, hi: c=2kp+1}
__device__ uint32_t g_wpk_lo[8 * ND];    // residual bf16x2

__device__ __forceinline__ uint32_t pk_bf16(float hi, float lo) {
    uint32_t r;
    asm("cvt.rn.bf16x2.f32 %0, %1, %2;" : "=r"(r) : "f"(hi), "f"(lo));
    return r;
}

// fp32 pair -> bf16x2 hi + bf16x2 residual
__device__ __forceinline__ void cvt_hilo(float2 f, uint32_t& h, uint32_t& l) {
    h = pk_bf16(f.y, f.x);
    float r0 = f.x - __uint_as_float(h << 16);
    float r1 = f.y - __uint_as_float(h & 0xFFFF0000u);
    l = pk_bf16(r1, r0);
}

// D = A*B + 0
__device__ __forceinline__ void mma_z(float& d0, float& d1, float& d2, float& d3,
                                      uint32_t a0, uint32_t a1, uint32_t a2, uint32_t a3,
                                      uint32_t b0, uint32_t b1) {
    asm("mma.sync.aligned.m16n8k16.row.col.f32.bf16.bf16.f32 "
        "{%0,%1,%2,%3},{%4,%5,%6,%7},{%8,%9},{%10,%11,%12,%13};"
        : "=f"(d0), "=f"(d1), "=f"(d2), "=f"(d3)
        : "r"(a0), "r"(a1), "r"(a2), "r"(a3), "r"(b0), "r"(b1),
          "f"(0.f), "f"(0.f), "f"(0.f), "f"(0.f));
}
// D += A*B
__device__ __forceinline__ void mma_a(float& d0, float& d1, float& d2, float& d3,
                                      uint32_t a0, uint32_t a1, uint32_t a2, uint32_t a3,
                                      uint32_t b0, uint32_t b1) {
    asm("mma.sync.aligned.m16n8k16.row.col.f32.bf16.bf16.f32 "
        "{%0,%1,%2,%3},{%4,%5,%6,%7},{%8,%9},{%0,%1,%2,%3};"
        : "+f"(d0), "+f"(d1), "+f"(d2), "+f"(d3)
        : "r"(a0), "r"(a1), "r"(a2), "r"(a3), "r"(b0), "r"(b1));
}

// ---------------------------------------------------------------------------
// Prologue
// ---------------------------------------------------------------------------
__global__ void prep_kernel(const float* __restrict__ z_embed,
                            const float* __restrict__ w1,
                            const float* __restrict__ b1) {
    int t = threadIdx.x;
    for (int i = t; i < NZ * ND; i += blockDim.x) {
        int z = i >> 6, d = i & 63;
        float s = b1[d];
#pragma unroll
        for (int c = 0; c < NC; c++)
            s += z_embed[z * NC + c] * w1[(NC + c) * ND + d];
        g_zpart[i] = s;
    }
    for (int i = t; i < 8 * ND; i += blockDim.x) {
        int kp = i >> 6, d = i & 63;
        float w0 = w1[(2 * kp) * ND + d];
        float w1v = w1[(2 * kp + 1) * ND + d];
        uint32_t hi = pk_bf16(w1v, w0);
        float h0 = __uint_as_float(hi << 16);
        float h1 = __uint_as_float(hi & 0xFFFF0000u);
        g_wpk_hi[i] = hi;
        g_wpk_lo[i] = pk_bf16(w1v - h1, w0 - h0);
    }
}

// ---------------------------------------------------------------------------
// Main: 1 warp = 1 pillar, HMMA bf16 3-term split, no smem
// ---------------------------------------------------------------------------
__global__ __launch_bounds__(256)
void bev_hmma(const float* __restrict__ vol,
              const float* __restrict__ gamma_,
              const float* __restrict__ beta_,
              float* __restrict__ out) {
    int tid = threadIdx.x;
    int warp = tid >> 5, lane = tid & 31;
    int g = lane >> 2, t = lane & 3;
    int pillar = blockIdx.x * 8 + warp;

    // B fragments (hoisted, loop-invariant): b0 covers k=2t,2t+1 (kpair t),
    // b1 covers k=2t+8,2t+9 (kpair t+4); column n = nt*8 + g.
    uint32_t BH0[8], BH1[8], BL0[8], BL1[8];
#pragma unroll
    for (int nt = 0; nt < 8; nt++) {
        int n = nt * 8 + g;
        BH0[nt] = g_wpk_hi[t * ND + n];
        BH1[nt] = g_wpk_hi[(t + 4) * ND + n];
        BL0[nt] = g_wpk_lo[t * ND + n];
        BL1[nt] = g_wpk_lo[(t + 4) * ND + n];
    }

    const float* base = vol + (size_t)pillar * (NZ * NC);
    float zsA[8], zsB[8];
#pragma unroll
    for (int nt = 0; nt < 8; nt++) { zsA[nt] = 0.f; zsB[nt] = 0.f; }

#pragma unroll 2
    for (int z0 = 0; z0 < NZ; z0 += 16) {
        // A fragment loads: a0=(row g, k 2t..2t+1), a1=(row g+8, same),
        // a2=(row g, k 2t+8..9), a3=(row g+8, k 2t+8..9)
        const float* rp = base + (z0 + g) * NC;
        float2 f0 = *(const float2*)(rp + 2 * t);            // row g,   k lo
        float2 f2 = *(const float2*)(rp + 2 * t + 8);        // row g,   k hi
        float2 f1 = *(const float2*)(rp + 8 * NC + 2 * t);     // row g+8, k lo
        float2 f3 = *(const float2*)(rp + 8 * NC + 2 * t + 8); // row g+8, k hi

        uint32_t ah0, ah1, ah2, ah3, al0, al1, al2, al3;
        cvt_hilo(f0, ah0, al0);
        cvt_hilo(f1, ah1, al1);
        cvt_hilo(f2, ah2, al2);
        cvt_hilo(f3, ah3, al3);

#pragma unroll
        for (int nt = 0; nt < 8; nt++) {
            float d0, d1, d2, d3;
            mma_z(d0, d1, d2, d3, ah0, ah1, ah2, ah3, BH0[nt], BH1[nt]);
            mma_a(d0, d1, d2, d3, ah0, ah1, ah2, ah3, BL0[nt], BL1[nt]);
            mma_a(d0, d1, d2, d3, al0, al1, al2, al3, BH0[nt], BH1[nt]);

            // D lane map: d0=(z0+g, 8nt+2t) d1=(z0+g, +1) d2=(z0+g+8, 8nt+2t) d3=(.., +1)
            float2 zp0 = *(const float2*)&g_zpart[(z0 + g) * ND + nt * 8 + 2 * t];
            float2 zp1 = *(const float2*)&g_zpart[(z0 + g + 8) * ND + nt * 8 + 2 * t];
            zsA[nt] += fmaxf(d0 + zp0.x, 0.f) + fmaxf(d2 + zp1.x, 0.f);
            zsB[nt] += fmaxf(d1 + zp0.y, 0.f) + fmaxf(d3 + zp1.y, 0.f);
        }
    }

    // Reduce over g (lanes differing in bits 2..4): offsets 4, 8, 16
#pragma unroll
    for (int nt = 0; nt < 8; nt++) {
#pragma unroll
        for (int o = 4; o <= 16; o <<= 1) {
            zsA[nt] += __shfl_xor_sync(0xffffffffu, zsA[nt], o);
            zsB[nt] += __shfl_xor_sync(0xffffffffu, zsB[nt], o);
        }
    }

    // LayerNorm stats: local 16 d-values per lane, then mix t-classes (1, 2)
    float s = 0.f, sq = 0.f;
#pragma unroll
    for (int nt = 0; nt < 8; nt++) {
        s += zsA[nt] + zsB[nt];
        sq += zsA[nt] * zsA[nt] + zsB[nt] * zsB[nt];
    }
    s  += __shfl_xor_sync(0xffffffffu, s, 1);
    s  += __shfl_xor_sync(0xffffffffu, s, 2);
    sq += __shfl_xor_sync(0xffffffffu, sq, 1);
    sq += __shfl_xor_sync(0xffffffffu, sq, 2);

    float mean = s * (1.0f / 64.0f);
    float var  = sq * (1.0f / 64.0f) - mean * mean;
    float inv  = rsqrtf(var + LN_EPS);

    if (lane < 4) {
        float* op = out + (size_t)pillar * ND;
#pragma unroll
        for (int nt = 0; nt < 8; nt++) {
            int d = nt * 8 + 2 * t;
            float2 ga = *(const float2*)&gamma_[d];
            float2 be = *(const float2*)&beta_[d];
            float2 o2;
            o2.x = (zsA[nt] - mean) * inv * ga.x + be.x;
            o2.y = (zsB[nt] - mean) * inv * ga.y + be.y;
            *(float2*)&op[d] = o2;
        }
    }
}

// ---------------------------------------------------------------------------
// Launch
// ---------------------------------------------------------------------------
extern "C" void kernel_launch(void* const* d_in, const int* in_sizes, int n_in,
                              void* d_out, int out_size) {
    const float* vol     = (const float*)d_in[0];
    const float* z_embed = (const float*)d_in[1];
    const float* w1      = (const float*)d_in[2];
    const float* b1      = (const float*)d_in[3];
    const float* gamma_  = (const float*)d_in[4];
    const float* beta_   = (const float*)d_in[5];
    float* out = (float*)d_out;

    prep_kernel<<<1, 256>>>(z_embed, w1, b1);
    bev_hmma<<<NP / 8, 256>>>(vol, gamma_, beta_, out);
}

// round 6
// speedup vs baseline: 3.3390x; 1.4439x over previous
#include <cuda_runtime.h>
#include <cuda_bf16.h>
#include <cstdint>

#define NZ 64
#define NC 16
#define ND 64
#define NP 65536
#define LN_EPS 1e-5f

// Prepped constants
__device__ uint32_t g_wpk_hi[8 * ND];    // [kpair][d] bf16x2 {lo: c=2kp, hi: c=2kp+1}
__device__ uint32_t g_wpk_lo[8 * ND];    // residual bf16x2
// zpart packed in MMA-fragment order: [j][z][t] float4 =
//   { zp[z][16j+2t], zp[z][16j+2t+1], zp[z][16j+8+2t], zp[z][16j+8+2t+1] }
__device__ float4 g_zpf[4 * NZ * 4];

__device__ __forceinline__ uint32_t pk_bf16(float hi, float lo) {
    uint32_t r;
    asm("cvt.rn.bf16x2.f32 %0, %1, %2;" : "=r"(r) : "f"(hi), "f"(lo));
    return r;
}

// fp32 pair -> bf16x2 hi + bf16x2 residual
__device__ __forceinline__ void cvt_hilo(float2 f, uint32_t& h, uint32_t& l) {
    h = pk_bf16(f.y, f.x);
    float r0 = f.x - __uint_as_float(h << 16);
    float r1 = f.y - __uint_as_float(h & 0xFFFF0000u);
    l = pk_bf16(r1, r0);
}

// D = A*B + 0
__device__ __forceinline__ void mma_z(float& d0, float& d1, float& d2, float& d3,
                                      uint32_t a0, uint32_t a1, uint32_t a2, uint32_t a3,
                                      uint32_t b0, uint32_t b1) {
    asm("mma.sync.aligned.m16n8k16.row.col.f32.bf16.bf16.f32 "
        "{%0,%1,%2,%3},{%4,%5,%6,%7},{%8,%9},{%10,%11,%12,%13};"
        : "=f"(d0), "=f"(d1), "=f"(d2), "=f"(d3)
        : "r"(a0), "r"(a1), "r"(a2), "r"(a3), "r"(b0), "r"(b1),
          "f"(0.f), "f"(0.f), "f"(0.f), "f"(0.f));
}
// D += A*B
__device__ __forceinline__ void mma_a(float& d0, float& d1, float& d2, float& d3,
                                      uint32_t a0, uint32_t a1, uint32_t a2, uint32_t a3,
                                      uint32_t b0, uint32_t b1) {
    asm("mma.sync.aligned.m16n8k16.row.col.f32.bf16.bf16.f32 "
        "{%0,%1,%2,%3},{%4,%5,%6,%7},{%8,%9},{%0,%1,%2,%3};"
        : "+f"(d0), "+f"(d1), "+f"(d2), "+f"(d3)
        : "r"(a0), "r"(a1), "r"(a2), "r"(a3), "r"(b0), "r"(b1));
}

// ---------------------------------------------------------------------------
// Prologue
// ---------------------------------------------------------------------------
__global__ void prep_kernel(const float* __restrict__ z_embed,
                            const float* __restrict__ w1,
                            const float* __restrict__ b1) {
    int tt = threadIdx.x;
    for (int i = tt; i < NZ * ND; i += blockDim.x) {
        int z = i >> 6, d = i & 63;
        float s = b1[d];
#pragma unroll
        for (int c = 0; c < NC; c++)
            s += z_embed[z * NC + c] * w1[(NC + c) * ND + d];
        // scatter into fragment layout
        int j = d >> 4, r = d & 15;
        int t = (r & 7) >> 1;
        int slot = ((r >> 3) << 1) | (r & 1);
        ((float*)g_zpf)[(((j * NZ) + z) * 4 + t) * 4 + slot] = s;
    }
    for (int i = tt; i < 8 * ND; i += blockDim.x) {
        int kp = i >> 6, d = i & 63;
        float w0 = w1[(2 * kp) * ND + d];
        float w1v = w1[(2 * kp + 1) * ND + d];
        uint32_t hi = pk_bf16(w1v, w0);
        float h0 = __uint_as_float(hi << 16);
        float h1 = __uint_as_float(hi & 0xFFFF0000u);
        g_wpk_hi[i] = hi;
        g_wpk_lo[i] = pk_bf16(w1v - h1, w0 - h0);
    }
}

// ---------------------------------------------------------------------------
// Main: 1 warp = 1 pillar, HMMA bf16 3-term split, coalesced zpart frags
// ---------------------------------------------------------------------------
__global__ __launch_bounds__(256)
void bev_hmma(const float* __restrict__ vol,
              const float* __restrict__ gamma_,
              const float* __restrict__ beta_,
              float* __restrict__ out) {
    int tid = threadIdx.x;
    int warp = tid >> 5, lane = tid & 31;
    int g = lane >> 2, t = lane & 3;
    int pillar = blockIdx.x * 8 + warp;

    // B fragments (hoisted, loop-invariant)
    uint32_t BH0[8], BH1[8], BL0[8], BL1[8];
#pragma unroll
    for (int nt = 0; nt < 8; nt++) {
        int n = nt * 8 + g;
        BH0[nt] = g_wpk_hi[t * ND + n];
        BH1[nt] = g_wpk_hi[(t + 4) * ND + n];
        BL0[nt] = g_wpk_lo[t * ND + n];
        BL1[nt] = g_wpk_lo[(t + 4) * ND + n];
    }

    const float* base = vol + (size_t)pillar * (NZ * NC);
    float zsA[8], zsB[8];
#pragma unroll
    for (int nt = 0; nt < 8; nt++) { zsA[nt] = 0.f; zsB[nt] = 0.f; }

#pragma unroll 2
    for (int z0 = 0; z0 < NZ; z0 += 16) {
        const float* rp = base + (z0 + g) * NC;
        float2 f0 = *(const float2*)(rp + 2 * t);              // row g,   k lo
        float2 f2 = *(const float2*)(rp + 2 * t + 8);          // row g,   k hi
        float2 f1 = *(const float2*)(rp + 8 * NC + 2 * t);     // row g+8, k lo
        float2 f3 = *(const float2*)(rp + 8 * NC + 2 * t + 8); // row g+8, k hi

        uint32_t ah0, ah1, ah2, ah3, al0, al1, al2, al3;
        cvt_hilo(f0, ah0, al0);
        cvt_hilo(f1, ah1, al1);
        cvt_hilo(f2, ah2, al2);
        cvt_hilo(f3, ah3, al3);

#pragma unroll
        for (int j = 0; j < 4; j++) {
            // coalesced fragment-ordered zpart: warp reads contiguous 512B
            float4 zq0 = g_zpf[j * (NZ * 4) + (z0 + g) * 4 + t];
            float4 zq1 = g_zpf[j * (NZ * 4) + (z0 + g + 8) * 4 + t];
#pragma unroll
            for (int h = 0; h < 2; h++) {
                int nt = 2 * j + h;
                float d0, d1, d2, d3;
                mma_z(d0, d1, d2, d3, ah0, ah1, ah2, ah3, BH0[nt], BH1[nt]);
                mma_a(d0, d1, d2, d3, ah0, ah1, ah2, ah3, BL0[nt], BL1[nt]);
                mma_a(d0, d1, d2, d3, al0, al1, al2, al3, BH0[nt], BH1[nt]);

                float zx0 = h ? zq0.z : zq0.x, zy0 = h ? zq0.w : zq0.y;
                float zx1 = h ? zq1.z : zq1.x, zy1 = h ? zq1.w : zq1.y;
                zsA[nt] += fmaxf(d0 + zx0, 0.f) + fmaxf(d2 + zx1, 0.f);
                zsB[nt] += fmaxf(d1 + zy0, 0.f) + fmaxf(d3 + zy1, 0.f);
            }
        }
    }

    // Reduce over g (lanes differing in bits 2..4): offsets 4, 8, 16
#pragma unroll
    for (int nt = 0; nt < 8; nt++) {
#pragma unroll
        for (int o = 4; o <= 16; o <<= 1) {
            zsA[nt] += __shfl_xor_sync(0xffffffffu, zsA[nt], o);
            zsB[nt] += __shfl_xor_sync(0xffffffffu, zsB[nt], o);
        }
    }

    // LayerNorm stats: local 16 d-values per lane, then mix t-classes (1, 2)
    float s = 0.f, sq = 0.f;
#pragma unroll
    for (int nt = 0; nt < 8; nt++) {
        s += zsA[nt] + zsB[nt];
        sq += zsA[nt] * zsA[nt] + zsB[nt] * zsB[nt];
    }
    s  += __shfl_xor_sync(0xffffffffu, s, 1);
    s  += __shfl_xor_sync(0xffffffffu, s, 2);
    sq += __shfl_xor_sync(0xffffffffu, sq, 1);
    sq += __shfl_xor_sync(0xffffffffu, sq, 2);

    float mean = s * (1.0f / 64.0f);
    float var  = sq * (1.0f / 64.0f) - mean * mean;
    float inv  = rsqrtf(var + LN_EPS);

    if (lane < 4) {
        float* op = out + (size_t)pillar * ND;
#pragma unroll
        for (int nt = 0; nt < 8; nt++) {
            int d = nt * 8 + 2 * t;
            float2 ga = *(const float2*)&gamma_[d];
            float2 be = *(const float2*)&beta_[d];
            float2 o2;
            o2.x = (zsA[nt] - mean) * inv * ga.x + be.x;
            o2.y = (zsB[nt] - mean) * inv * ga.y + be.y;
            *(float2*)&op[d] = o2;
        }
    }
}

// ---------------------------------------------------------------------------
// Launch
// ---------------------------------------------------------------------------
extern "C" void kernel_launch(void* const* d_in, const int* in_sizes, int n_in,
                              void* d_out, int out_size) {
    const float* vol     = (const float*)d_in[0];
    const float* z_embed = (const float*)d_in[1];
    const float* w1      = (const float*)d_in[2];
    const float* b1      = (const float*)d_in[3];
    const float* gamma_  = (const float*)d_in[4];
    const float* beta_   = (const float*)d_in[5];
    float* out = (float*)d_out;

    prep_kernel<<<1, 256>>>(z_embed, w1, b1);
    bev_hmma<<<NP / 8, 256>>>(vol, gamma_, beta_, out);
}

// round 7
// speedup vs baseline: 3.5673x; 1.0684x over previous
#include <cuda_runtime.h>
#include <cuda_bf16.h>
#include <cstdint>

#define NZ 64
#define NC 16
#define ND 64
#define NP 65536
#define NPAIR (NP / 2)
#define LN_EPS 1e-5f

// Prepped constants
__device__ uint32_t g_wpk_hi[8 * ND];    // [kpair][d] bf16x2 {lo: c=2kp, hi: c=2kp+1}
__device__ uint32_t g_wpk_lo[8 * ND];    // residual bf16x2
// zpart in MMA-fragment order: [j][z][t] float4 =
//   { zp[z][16j+2t], zp[z][16j+2t+1], zp[z][16j+8+2t], zp[z][16j+8+2t+1] }
__device__ float4 g_zpf[4 * NZ * 4];

__device__ __forceinline__ uint32_t pk_bf16(float hi, float lo) {
    uint32_t r;
    asm("cvt.rn.bf16x2.f32 %0, %1, %2;" : "=r"(r) : "f"(hi), "f"(lo));
    return r;
}

// float4 (c 4t..4t+3) -> two hi bf16x2 + two residual bf16x2
__device__ __forceinline__ void cvt4(float4 f, uint32_t& hxy, uint32_t& hzw,
                                     uint32_t& lxy, uint32_t& lzw) {
    hxy = pk_bf16(f.y, f.x);
    hzw = pk_bf16(f.w, f.z);
    float r0 = f.x - __uint_as_float(hxy << 16);
    float r1 = f.y - __uint_as_float(hxy & 0xFFFF0000u);
    float r2 = f.z - __uint_as_float(hzw << 16);
    float r3 = f.w - __uint_as_float(hzw & 0xFFFF0000u);
    lxy = pk_bf16(r1, r0);
    lzw = pk_bf16(r3, r2);
}

// D = A*B + 0
__device__ __forceinline__ void mma_z(float& d0, float& d1, float& d2, float& d3,
                                      uint32_t a0, uint32_t a1, uint32_t a2, uint32_t a3,
                                      uint32_t b0, uint32_t b1) {
    asm("mma.sync.aligned.m16n8k16.row.col.f32.bf16.bf16.f32 "
        "{%0,%1,%2,%3},{%4,%5,%6,%7},{%8,%9},{%10,%11,%12,%13};"
        : "=f"(d0), "=f"(d1), "=f"(d2), "=f"(d3)
        : "r"(a0), "r"(a1), "r"(a2), "r"(a3), "r"(b0), "r"(b1),
          "f"(0.f), "f"(0.f), "f"(0.f), "f"(0.f));
}
// D += A*B
__device__ __forceinline__ void mma_a(float& d0, float& d1, float& d2, float& d3,
                                      uint32_t a0, uint32_t a1, uint32_t a2, uint32_t a3,
                                      uint32_t b0, uint32_t b1) {
    asm("mma.sync.aligned.m16n8k16.row.col.f32.bf16.bf16.f32 "
        "{%0,%1,%2,%3},{%4,%5,%6,%7},{%8,%9},{%0,%1,%2,%3};"
        : "+f"(d0), "+f"(d1), "+f"(d2), "+f"(d3)
        : "r"(a0), "r"(a1), "r"(a2), "r"(a3), "r"(b0), "r"(b1));
}

// ---------------------------------------------------------------------------
// Prologue (unchanged from R6)
// ---------------------------------------------------------------------------
__global__ void prep_kernel(const float* __restrict__ z_embed,
                            const float* __restrict__ w1,
                            const float* __restrict__ b1) {
    int tt = threadIdx.x;
    for (int i = tt; i < NZ * ND; i += blockDim.x) {
        int z = i >> 6, d = i & 63;
        float s = b1[d];
#pragma unroll
        for (int c = 0; c < NC; c++)
            s += z_embed[z * NC + c] * w1[(NC + c) * ND + d];
        int j = d >> 4, r = d & 15;
        int t = (r & 7) >> 1;
        int slot = ((r >> 3) << 1) | (r & 1);
        ((float*)g_zpf)[(((j * NZ) + z) * 4 + t) * 4 + slot] = s;
    }
    for (int i = tt; i < 8 * ND; i += blockDim.x) {
        int kp = i >> 6, d = i & 63;
        float w0 = w1[(2 * kp) * ND + d];
        float w1v = w1[(2 * kp + 1) * ND + d];
        uint32_t hi = pk_bf16(w1v, w0);
        float h0 = __uint_as_float(hi << 16);
        float h1 = __uint_as_float(hi & 0xFFFF0000u);
        g_wpk_hi[i] = hi;
        g_wpk_lo[i] = pk_bf16(w1v - h1, w0 - h0);
    }
}

// ---------------------------------------------------------------------------
// Main: 1 warp = 2 pillars (pair); zpart fragments shared across the pair.
// K-permuted: lane t owns c = 4t..4t+3 -> single LDG.128 per fragment row.
// ---------------------------------------------------------------------------
__global__ __launch_bounds__(128)
void bev_hmma(const float* __restrict__ vol,
              const float* __restrict__ gamma_,
              const float* __restrict__ beta_,
              float* __restrict__ out) {
    int tid = threadIdx.x;
    int warp = tid >> 5, lane = tid & 31;
    int g = lane >> 2, t = lane & 3;
    int pair = blockIdx.x * 4 + warp;

    // B fragments under K-permutation: b0 <-> c(4t,4t+1)=kp 2t, b1 <-> kp 2t+1
    uint32_t BH0[8], BH1[8], BL0[8], BL1[8];
#pragma unroll
    for (int nt = 0; nt < 8; nt++) {
        int n = nt * 8 + g;
        BH0[nt] = g_wpk_hi[(2 * t) * ND + n];
        BH1[nt] = g_wpk_hi[(2 * t + 1) * ND + n];
        BL0[nt] = g_wpk_lo[(2 * t) * ND + n];
        BL1[nt] = g_wpk_lo[(2 * t + 1) * ND + n];
    }

    const float* baseA = vol + (size_t)pair * 2048;   // pillar 2*pair
    const float* baseB = baseA + 1024;                // pillar 2*pair+1

    float zsA0[8], zsB0[8], zsA1[8], zsB1[8];
#pragma unroll
    for (int nt = 0; nt < 8; nt++) {
        zsA0[nt] = 0.f; zsB0[nt] = 0.f; zsA1[nt] = 0.f; zsB1[nt] = 0.f;
    }

#pragma unroll
    for (int z0 = 0; z0 < NZ; z0 += 16) {
        // one LDG.128 per fragment row (K-permuted), both pillars
        const float* rA = baseA + (z0 + g) * NC + 4 * t;
        const float* rB = baseB + (z0 + g) * NC + 4 * t;
        float4 fa_lo = *(const float4*)rA;
        float4 fa_hi = *(const float4*)(rA + 8 * NC);
        float4 fb_lo = *(const float4*)rB;
        float4 fb_hi = *(const float4*)(rB + 8 * NC);

        // A fragments: a0 = row g c(4t..4t+1), a2 = row g c(4t+2..4t+3), a1/a3 rows +8
        uint32_t aA0, aA2, lA0, lA2, aA1, aA3, lA1, lA3;
        uint32_t aB0, aB2, lB0, lB2, aB1, aB3, lB1, lB3;
        cvt4(fa_lo, aA0, aA2, lA0, lA2);
        cvt4(fa_hi, aA1, aA3, lA1, lA3);
        cvt4(fb_lo, aB0, aB2, lB0, lB2);
        cvt4(fb_hi, aB1, aB3, lB1, lB3);

#pragma unroll
        for (int j = 0; j < 4; j++) {
            // shared zpart fragments (coalesced 512B per warp-read)
            float4 zq0 = g_zpf[j * (NZ * 4) + (z0 + g) * 4 + t];
            float4 zq1 = g_zpf[j * (NZ * 4) + (z0 + g + 8) * 4 + t];
#pragma unroll
            for (int h = 0; h < 2; h++) {
                int nt = 2 * j + h;
                float zx0 = h ? zq0.z : zq0.x, zy0 = h ? zq0.w : zq0.y;
                float zx1 = h ? zq1.z : zq1.x, zy1 = h ? zq1.w : zq1.y;

                float d0, d1, d2, d3;
                mma_z(d0, d1, d2, d3, aA0, aA1, aA2, aA3, BH0[nt], BH1[nt]);
                mma_a(d0, d1, d2, d3, aA0, aA1, aA2, aA3, BL0[nt], BL1[nt]);
                mma_a(d0, d1, d2, d3, lA0, lA1, lA2, lA3, BH0[nt], BH1[nt]);
                zsA0[nt] += fmaxf(d0 + zx0, 0.f) + fmaxf(d2 + zx1, 0.f);
                zsB0[nt] += fmaxf(d1 + zy0, 0.f) + fmaxf(d3 + zy1, 0.f);

                mma_z(d0, d1, d2, d3, aB0, aB1, aB2, aB3, BH0[nt], BH1[nt]);
                mma_a(d0, d1, d2, d3, aB0, aB1, aB2, aB3, BL0[nt], BL1[nt]);
                mma_a(d0, d1, d2, d3, lB0, lB1, lB2, lB3, BH0[nt], BH1[nt]);
                zsA1[nt] += fmaxf(d0 + zx0, 0.f) + fmaxf(d2 + zx1, 0.f);
                zsB1[nt] += fmaxf(d1 + zy0, 0.f) + fmaxf(d3 + zy1, 0.f);
            }
        }
    }

    // ---- per-pillar reduction + LN + store
#pragma unroll
    for (int p = 0; p < 2; p++) {
        float* zsA = p ? zsA1 : zsA0;
        float* zsB = p ? zsB1 : zsB0;
#pragma unroll
        for (int nt = 0; nt < 8; nt++) {
#pragma unroll
            for (int o = 4; o <= 16; o <<= 1) {
                zsA[nt] += __shfl_xor_sync(0xffffffffu, zsA[nt], o);
                zsB[nt] += __shfl_xor_sync(0xffffffffu, zsB[nt], o);
            }
        }
        float s = 0.f, sq = 0.f;
#pragma unroll
        for (int nt = 0; nt < 8; nt++) {
            s += zsA[nt] + zsB[nt];
            sq += zsA[nt] * zsA[nt] + zsB[nt] * zsB[nt];
        }
        s  += __shfl_xor_sync(0xffffffffu, s, 1);
        s  += __shfl_xor_sync(0xffffffffu, s, 2);
        sq += __shfl_xor_sync(0xffffffffu, sq, 1);
        sq += __shfl_xor_sync(0xffffffffu, sq, 2);

        float mean = s * (1.0f / 64.0f);
        float var  = sq * (1.0f / 64.0f) - mean * mean;
        float inv  = rsqrtf(var + LN_EPS);

        if (lane < 4) {
            float* op = out + ((size_t)pair * 2 + p) * ND;
#pragma unroll
            for (int nt = 0; nt < 8; nt++) {
                int d = nt * 8 + 2 * t;
                float2 ga = *(const float2*)&gamma_[d];
                float2 be = *(const float2*)&beta_[d];
                float2 o2;
                o2.x = (zsA[nt] - mean) * inv * ga.x + be.x;
                o2.y = (zsB[nt] - mean) * inv * ga.y + be.y;
                *(float2*)&op[d] = o2;
            }
        }
    }
}

// ---------------------------------------------------------------------------
// Launch
// ---------------------------------------------------------------------------
extern "C" void kernel_launch(void* const* d_in, const int* in_sizes, int n_in,
                              void* d_out, int out_size) {
    const float* vol     = (const float*)d_in[0];
    const float* z_embed = (const float*)d_in[1];
    const float* w1      = (const float*)d_in[2];
    const float* b1      = (const float*)d_in[3];
    const float* gamma_  = (const float*)d_in[4];
    const float* beta_   = (const float*)d_in[5];
    float* out = (float*)d_out;

    prep_kernel<<<1, 256>>>(z_embed, w1, b1);
    bev_hmma<<<NPAIR / 4, 128>>>(vol, gamma_, beta_, out);
}

// round 8
// speedup vs baseline: 4.4537x; 1.2485x over previous
#include <cuda_runtime.h>
#include <cuda_bf16.h>
#include <cstdint>

#define NZ 64
#define NC 16
#define ND 64
#define NP 65536
#define NPAIR (NP / 2)
#define LN_EPS 1e-5f

// Prepped constants
__device__ uint32_t g_wpk_hi[8 * ND];    // [kpair][d] bf16x2 {lo: c=2kp, hi: c=2kp+1}
__device__ uint32_t g_wpk_lo[8 * ND];    // residual bf16x2
// zpart in MMA-fragment order: [j][z][t] float4 =
//   { zp[z][16j+2t], zp[z][16j+2t+1], zp[z][16j+8+2t], zp[z][16j+8+2t+1] }
__device__ float4 g_zpf[4 * NZ * 4];

__device__ __forceinline__ uint32_t pk_bf16(float hi, float lo) {
    uint32_t r;
    asm("cvt.rn.bf16x2.f32 %0, %1, %2;" : "=r"(r) : "f"(hi), "f"(lo));
    return r;
}

// float4 (c 4t..4t+3) -> two hi bf16x2 + two residual bf16x2
__device__ __forceinline__ void cvt4(float4 f, uint32_t& hxy, uint32_t& hzw,
                                     uint32_t& lxy, uint32_t& lzw) {
    hxy = pk_bf16(f.y, f.x);
    hzw = pk_bf16(f.w, f.z);
    float r0 = f.x - __uint_as_float(hxy << 16);
    float r1 = f.y - __uint_as_float(hxy & 0xFFFF0000u);
    float r2 = f.z - __uint_as_float(hzw << 16);
    float r3 = f.w - __uint_as_float(hzw & 0xFFFF0000u);
    lxy = pk_bf16(r1, r0);
    lzw = pk_bf16(r3, r2);
}

// D = A*B + C (zpart folded into accumulator init)
__device__ __forceinline__ void mma_c(float& d0, float& d1, float& d2, float& d3,
                                      uint32_t a0, uint32_t a1, uint32_t a2, uint32_t a3,
                                      uint32_t b0, uint32_t b1,
                                      float c0, float c1, float c2, float c3) {
    asm("mma.sync.aligned.m16n8k16.row.col.f32.bf16.bf16.f32 "
        "{%0,%1,%2,%3},{%4,%5,%6,%7},{%8,%9},{%10,%11,%12,%13};"
        : "=f"(d0), "=f"(d1), "=f"(d2), "=f"(d3)
        : "r"(a0), "r"(a1), "r"(a2), "r"(a3), "r"(b0), "r"(b1),
          "f"(c0), "f"(c1), "f"(c2), "f"(c3));
}
// D += A*B
__device__ __forceinline__ void mma_a(float& d0, float& d1, float& d2, float& d3,
                                      uint32_t a0, uint32_t a1, uint32_t a2, uint32_t a3,
                                      uint32_t b0, uint32_t b1) {
    asm("mma.sync.aligned.m16n8k16.row.col.f32.bf16.bf16.f32 "
        "{%0,%1,%2,%3},{%4,%5,%6,%7},{%8,%9},{%0,%1,%2,%3};"
        : "+f"(d0), "+f"(d1), "+f"(d2), "+f"(d3)
        : "r"(a0), "r"(a1), "r"(a2), "r"(a3), "r"(b0), "r"(b1));
}

// ---------------------------------------------------------------------------
// Prologue — now grid-wide (32 blocks), not a serial single block
// ---------------------------------------------------------------------------
__global__ void prep_kernel(const float* __restrict__ z_embed,
                            const float* __restrict__ w1,
                            const float* __restrict__ b1) {
    int tt = blockIdx.x * blockDim.x + threadIdx.x;
    int stride = gridDim.x * blockDim.x;
    for (int i = tt; i < NZ * ND; i += stride) {
        int z = i >> 6, d = i & 63;
        float s = b1[d];
#pragma unroll
        for (int c = 0; c < NC; c++)
            s += z_embed[z * NC + c] * w1[(NC + c) * ND + d];
        int j = d >> 4, r = d & 15;
        int t = (r & 7) >> 1;
        int slot = ((r >> 3) << 1) | (r & 1);
        ((float*)g_zpf)[(((j * NZ) + z) * 4 + t) * 4 + slot] = s;
    }
    for (int i = tt; i < 8 * ND; i += stride) {
        int kp = i >> 6, d = i & 63;
        float w0 = w1[(2 * kp) * ND + d];
        float w1v = w1[(2 * kp + 1) * ND + d];
        uint32_t hi = pk_bf16(w1v, w0);
        float h0 = __uint_as_float(hi << 16);
        float h1 = __uint_as_float(hi & 0xFFFF0000u);
        g_wpk_hi[i] = hi;
        g_wpk_lo[i] = pk_bf16(w1v - h1, w0 - h0);
    }
}

// ---------------------------------------------------------------------------
// Main: 1 warp = 2 pillars; zpart folded into MMA C-operand
// ---------------------------------------------------------------------------
__global__ __launch_bounds__(128, 4)
void bev_hmma(const float* __restrict__ vol,
              const float* __restrict__ gamma_,
              const float* __restrict__ beta_,
              float* __restrict__ out) {
    int tid = threadIdx.x;
    int warp = tid >> 5, lane = tid & 31;
    int g = lane >> 2, t = lane & 3;
    int pair = blockIdx.x * 4 + warp;

    // B fragments under K-permutation: b0 <-> kp 2t, b1 <-> kp 2t+1
    uint32_t BH0[8], BH1[8], BL0[8], BL1[8];
#pragma unroll
    for (int nt = 0; nt < 8; nt++) {
        int n = nt * 8 + g;
        BH0[nt] = g_wpk_hi[(2 * t) * ND + n];
        BH1[nt] = g_wpk_hi[(2 * t + 1) * ND + n];
        BL0[nt] = g_wpk_lo[(2 * t) * ND + n];
        BL1[nt] = g_wpk_lo[(2 * t + 1) * ND + n];
    }

    const float* baseA = vol + (size_t)pair * 2048;   // pillar 2*pair
    const float* baseB = baseA + 1024;                // pillar 2*pair+1

    float zsA0[8], zsB0[8], zsA1[8], zsB1[8];
#pragma unroll
    for (int nt = 0; nt < 8; nt++) {
        zsA0[nt] = 0.f; zsB0[nt] = 0.f; zsA1[nt] = 0.f; zsB1[nt] = 0.f;
    }

#pragma unroll
    for (int z0 = 0; z0 < NZ; z0 += 16) {
        const float* rA = baseA + (z0 + g) * NC + 4 * t;
        const float* rB = baseB + (z0 + g) * NC + 4 * t;
        float4 fa_lo = *(const float4*)rA;
        float4 fa_hi = *(const float4*)(rA + 8 * NC);
        float4 fb_lo = *(const float4*)rB;
        float4 fb_hi = *(const float4*)(rB + 8 * NC);

        uint32_t aA0, aA2, lA0, lA2, aA1, aA3, lA1, lA3;
        uint32_t aB0, aB2, lB0, lB2, aB1, aB3, lB1, lB3;
        cvt4(fa_lo, aA0, aA2, lA0, lA2);
        cvt4(fa_hi, aA1, aA3, lA1, lA3);
        cvt4(fb_lo, aB0, aB2, lB0, lB2);
        cvt4(fb_hi, aB1, aB3, lB1, lB3);

#pragma unroll
        for (int j = 0; j < 4; j++) {
            float4 zq0 = g_zpf[j * (NZ * 4) + (z0 + g) * 4 + t];
            float4 zq1 = g_zpf[j * (NZ * 4) + (z0 + g + 8) * 4 + t];
#pragma unroll
            for (int h = 0; h < 2; h++) {
                int nt = 2 * j + h;
                float c0 = h ? zq0.z : zq0.x, c1 = h ? zq0.w : zq0.y;
                float c2 = h ? zq1.z : zq1.x, c3 = h ? zq1.w : zq1.y;

                float d0, d1, d2, d3;
                mma_c(d0, d1, d2, d3, aA0, aA1, aA2, aA3, BH0[nt], BH1[nt],
                      c0, c1, c2, c3);
                mma_a(d0, d1, d2, d3, aA0, aA1, aA2, aA3, BL0[nt], BL1[nt]);
                mma_a(d0, d1, d2, d3, lA0, lA1, lA2, lA3, BH0[nt], BH1[nt]);
                zsA0[nt] += fmaxf(d0, 0.f) + fmaxf(d2, 0.f);
                zsB0[nt] += fmaxf(d1, 0.f) + fmaxf(d3, 0.f);

                mma_c(d0, d1, d2, d3, aB0, aB1, aB2, aB3, BH0[nt], BH1[nt],
                      c0, c1, c2, c3);
                mma_a(d0, d1, d2, d3, aB0, aB1, aB2, aB3, BL0[nt], BL1[nt]);
                mma_a(d0, d1, d2, d3, lB0, lB1, lB2, lB3, BH0[nt], BH1[nt]);
                zsA1[nt] += fmaxf(d0, 0.f) + fmaxf(d2, 0.f);
                zsB1[nt] += fmaxf(d1, 0.f) + fmaxf(d3, 0.f);
            }
        }
    }

    // ---- per-pillar reduction + LN + store
#pragma unroll
    for (int p = 0; p < 2; p++) {
        float* zsA = p ? zsA1 : zsA0;
        float* zsB = p ? zsB1 : zsB0;
#pragma unroll
        for (int nt = 0; nt < 8; nt++) {
#pragma unroll
            for (int o = 4; o <= 16; o <<= 1) {
                zsA[nt] += __shfl_xor_sync(0xffffffffu, zsA[nt], o);
                zsB[nt] += __shfl_xor_sync(0xffffffffu, zsB[nt], o);
            }
        }
        float s = 0.f, sq = 0.f;
#pragma unroll
        for (int nt = 0; nt < 8; nt++) {
            s += zsA[nt] + zsB[nt];
            sq += zsA[nt] * zsA[nt] + zsB[nt] * zsB[nt];
        }
        s  += __shfl_xor_sync(0xffffffffu, s, 1);
        s  += __shfl_xor_sync(0xffffffffu, s, 2);
        sq += __shfl_xor_sync(0xffffffffu, sq, 1);
        sq += __shfl_xor_sync(0xffffffffu, sq, 2);

        float mean = s * (1.0f / 64.0f);
        float var  = sq * (1.0f / 64.0f) - mean * mean;
        float inv  = rsqrtf(var + LN_EPS);

        if (lane < 4) {
            float* op = out + ((size_t)pair * 2 + p) * ND;
#pragma unroll
            for (int nt = 0; nt < 8; nt++) {
                int d = nt * 8 + 2 * t;
                float2 ga = *(const float2*)&gamma_[d];
                float2 be = *(const float2*)&beta_[d];
                float2 o2;
                o2.x = (zsA[nt] - mean) * inv * ga.x + be.x;
                o2.y = (zsB[nt] - mean) * inv * ga.y + be.y;
                *(float2*)&op[d] = o2;
            }
        }
    }
}

// ---------------------------------------------------------------------------
// Launch
// ---------------------------------------------------------------------------
extern "C" void kernel_launch(void* const* d_in, const int* in_sizes, int n_in,
                              void* d_out, int out_size) {
    const float* vol     = (const float*)d_in[0];
    const float* z_embed = (const float*)d_in[1];
    const float* w1      = (const float*)d_in[2];
    const float* b1      = (const float*)d_in[3];
    const float* gamma_  = (const float*)d_in[4];
    const float* beta_   = (const float*)d_in[5];
    float* out = (float*)d_out;

    prep_kernel<<<32, 256>>>(z_embed, w1, b1);
    bev_hmma<<<NPAIR / 4, 128>>>(vol, gamma_, beta_, out);
}

// round 10
// speedup vs baseline: 4.4700x; 1.0037x over previous
#include <cuda_runtime.h>
#include <cuda_bf16.h>
#include <cstdint>

#define NZ 64
#define NC 16
#define ND 64
#define NP 65536
#define NPAIR (NP / 2)
#define LN_EPS 1e-5f

typedef unsigned long long ull;

// Prepped constants
__device__ uint32_t g_wpk_hi[8 * ND];    // [kpair][d] bf16x2 {lo: c=2kp, hi: c=2kp+1}
__device__ uint32_t g_wpk_lo[8 * ND];    // residual bf16x2
// zpart in MMA-fragment order: [j][z][t] float4
__device__ float4 g_zpf[4 * NZ * 4];

__device__ __forceinline__ uint32_t pk_bf16(float hi, float lo) {
    uint32_t r;
    asm("cvt.rn.bf16x2.f32 %0, %1, %2;" : "=r"(r) : "f"(hi), "f"(lo));
    return r;
}

// float4 (c 4t..4t+3) -> two hi bf16x2 + two residual bf16x2
__device__ __forceinline__ void cvt4(float4 f, uint32_t& hxy, uint32_t& hzw,
                                     uint32_t& lxy, uint32_t& lzw) {
    hxy = pk_bf16(f.y, f.x);
    hzw = pk_bf16(f.w, f.z);
    float r0 = f.x - __uint_as_float(hxy << 16);
    float r1 = f.y - __uint_as_float(hxy & 0xFFFF0000u);
    float r2 = f.z - __uint_as_float(hzw << 16);
    float r3 = f.w - __uint_as_float(hzw & 0xFFFF0000u);
    lxy = pk_bf16(r1, r0);
    lzw = pk_bf16(r3, r2);
}

// D = A*B + C (zpart folded into accumulator init)
__device__ __forceinline__ void mma_c(float& d0, float& d1, float& d2, float& d3,
                                      uint32_t a0, uint32_t a1, uint32_t a2, uint32_t a3,
                                      uint32_t b0, uint32_t b1,
                                      float c0, float c1, float c2, float c3) {
    asm("mma.sync.aligned.m16n8k16.row.col.f32.bf16.bf16.f32 "
        "{%0,%1,%2,%3},{%4,%5,%6,%7},{%8,%9},{%10,%11,%12,%13};"
        : "=f"(d0), "=f"(d1), "=f"(d2), "=f"(d3)
        : "r"(a0), "r"(a1), "r"(a2), "r"(a3), "r"(b0), "r"(b1),
          "f"(c0), "f"(c1), "f"(c2), "f"(c3));
}
// D += A*B
__device__ __forceinline__ void mma_a(float& d0, float& d1, float& d2, float& d3,
                                      uint32_t a0, uint32_t a1, uint32_t a2, uint32_t a3,
                                      uint32_t b0, uint32_t b1) {
    asm("mma.sync.aligned.m16n8k16.row.col.f32.bf16.bf16.f32 "
        "{%0,%1,%2,%3},{%4,%5,%6,%7},{%8,%9},{%0,%1,%2,%3};"
        : "+f"(d0), "+f"(d1), "+f"(d2), "+f"(d3)
        : "r"(a0), "r"(a1), "r"(a2), "r"(a3), "r"(b0), "r"(b1));
}

// relu the 4 MMA outputs (scalar FMNMX) and accumulate into the packed
// accumulator with two packed adds: acc.lo += r0 + r2 ; acc.hi += r1 + r3.
// Pairing done inside one asm block so ptxas can allocate r0/r1 (r2/r3)
// adjacently and fold the mov.b64s.
__device__ __forceinline__ void relu_acc2(ull& acc, float d0, float d1,
                                          float d2, float d3) {
    asm("{\n\t"
        ".reg .f32 r0, r1, r2, r3;\n\t"
        ".reg .b64 p, q;\n\t"
        "max.f32 r0, %1, 0f00000000;\n\t"
        "max.f32 r1, %2, 0f00000000;\n\t"
        "max.f32 r2, %3, 0f00000000;\n\t"
        "max.f32 r3, %4, 0f00000000;\n\t"
        "mov.b64 p, {r0, r1};\n\t"
        "mov.b64 q, {r2, r3};\n\t"
        "add.rn.f32x2 p, p, q;\n\t"
        "add.rn.f32x2 %0, %0, p;\n\t"
        "}"
        : "+l"(acc)
        : "f"(d0), "f"(d1), "f"(d2), "f"(d3));
}
__device__ __forceinline__ void unpk64(ull v, float& a, float& b) {
    asm("mov.b64 {%0, %1}, %2;" : "=f"(a), "=f"(b) : "l"(v));
}

// ---------------------------------------------------------------------------
// Prologue — grid-wide
// ---------------------------------------------------------------------------
__global__ void prep_kernel(const float* __restrict__ z_embed,
                            const float* __restrict__ w1,
                            const float* __restrict__ b1) {
    int tt = blockIdx.x * blockDim.x + threadIdx.x;
    int stride = gridDim.x * blockDim.x;
    for (int i = tt; i < NZ * ND; i += stride) {
        int z = i >> 6, d = i & 63;
        float s = b1[d];
#pragma unroll
        for (int c = 0; c < NC; c++)
            s += z_embed[z * NC + c] * w1[(NC + c) * ND + d];
        int j = d >> 4, r = d & 15;
        int t = (r & 7) >> 1;
        int slot = ((r >> 3) << 1) | (r & 1);
        ((float*)g_zpf)[(((j * NZ) + z) * 4 + t) * 4 + slot] = s;
    }
    for (int i = tt; i < 8 * ND; i += stride) {
        int kp = i >> 6, d = i & 63;
        float w0 = w1[(2 * kp) * ND + d];
        float w1v = w1[(2 * kp + 1) * ND + d];
        uint32_t hi = pk_bf16(w1v, w0);
        float h0 = __uint_as_float(hi << 16);
        float h1 = __uint_as_float(hi & 0xFFFF0000u);
        g_wpk_hi[i] = hi;
        g_wpk_lo[i] = pk_bf16(w1v - h1, w0 - h0);
    }
}

// ---------------------------------------------------------------------------
// Main: 1 warp = 2 pillars; packed accumulate epilogue
// ---------------------------------------------------------------------------
__global__ __launch_bounds__(128, 4)
void bev_hmma(const float* __restrict__ vol,
              const float* __restrict__ gamma_,
              const float* __restrict__ beta_,
              float* __restrict__ out) {
    int tid = threadIdx.x;
    int warp = tid >> 5, lane = tid & 31;
    int g = lane >> 2, t = lane & 3;
    int pair = blockIdx.x * 4 + warp;

    // B fragments under K-permutation: b0 <-> kp 2t, b1 <-> kp 2t+1
    uint32_t BH0[8], BH1[8], BL0[8], BL1[8];
#pragma unroll
    for (int nt = 0; nt < 8; nt++) {
        int n = nt * 8 + g;
        BH0[nt] = g_wpk_hi[(2 * t) * ND + n];
        BH1[nt] = g_wpk_hi[(2 * t + 1) * ND + n];
        BL0[nt] = g_wpk_lo[(2 * t) * ND + n];
        BL1[nt] = g_wpk_lo[(2 * t + 1) * ND + n];
    }

    const float* baseA = vol + (size_t)pair * 2048;   // pillar 2*pair
    const float* baseB = baseA + 1024;                // pillar 2*pair+1

    // packed accumulators: lo word = even-d col, hi word = odd-d col
    ull zs0[8], zs1[8];
#pragma unroll
    for (int nt = 0; nt < 8; nt++) { zs0[nt] = 0ULL; zs1[nt] = 0ULL; }

#pragma unroll
    for (int z0 = 0; z0 < NZ; z0 += 16) {
        const float* rA = baseA + (z0 + g) * NC + 4 * t;
        const float* rB = baseB + (z0 + g) * NC + 4 * t;
        float4 fa_lo = *(const float4*)rA;
        float4 fa_hi = *(const float4*)(rA + 8 * NC);
        float4 fb_lo = *(const float4*)rB;
        float4 fb_hi = *(const float4*)(rB + 8 * NC);

        uint32_t aA0, aA2, lA0, lA2, aA1, aA3, lA1, lA3;
        uint32_t aB0, aB2, lB0, lB2, aB1, aB3, lB1, lB3;
        cvt4(fa_lo, aA0, aA2, lA0, lA2);
        cvt4(fa_hi, aA1, aA3, lA1, lA3);
        cvt4(fb_lo, aB0, aB2, lB0, lB2);
        cvt4(fb_hi, aB1, aB3, lB1, lB3);

#pragma unroll
        for (int j = 0; j < 4; j++) {
            float4 zq0 = g_zpf[j * (NZ * 4) + (z0 + g) * 4 + t];
            float4 zq1 = g_zpf[j * (NZ * 4) + (z0 + g + 8) * 4 + t];
#pragma unroll
            for (int h = 0; h < 2; h++) {
                int nt = 2 * j + h;
                float c0 = h ? zq0.z : zq0.x, c1 = h ? zq0.w : zq0.y;
                float c2 = h ? zq1.z : zq1.x, c3 = h ? zq1.w : zq1.y;

                float d0, d1, d2, d3;
                mma_c(d0, d1, d2, d3, aA0, aA1, aA2, aA3, BH0[nt], BH1[nt],
                      c0, c1, c2, c3);
                mma_a(d0, d1, d2, d3, aA0, aA1, aA2, aA3, BL0[nt], BL1[nt]);
                mma_a(d0, d1, d2, d3, lA0, lA1, lA2, lA3, BH0[nt], BH1[nt]);
                relu_acc2(zs0[nt], d0, d1, d2, d3);

                mma_c(d0, d1, d2, d3, aB0, aB1, aB2, aB3, BH0[nt], BH1[nt],
                      c0, c1, c2, c3);
                mma_a(d0, d1, d2, d3, aB0, aB1, aB2, aB3, BL0[nt], BL1[nt]);
                mma_a(d0, d1, d2, d3, lB0, lB1, lB2, lB3, BH0[nt], BH1[nt]);
                relu_acc2(zs1[nt], d0, d1, d2, d3);
            }
        }
    }

    // ---- per-pillar reduction + LN + store
#pragma unroll
    for (int p = 0; p < 2; p++) {
        float zsA[8], zsB[8];
#pragma unroll
        for (int nt = 0; nt < 8; nt++)
            unpk64(p ? zs1[nt] : zs0[nt], zsA[nt], zsB[nt]);
#pragma unroll
        for (int nt = 0; nt < 8; nt++) {
#pragma unroll
            for (int o = 4; o <= 16; o <<= 1) {
                zsA[nt] += __shfl_xor_sync(0xffffffffu, zsA[nt], o);
                zsB[nt] += __shfl_xor_sync(0xffffffffu, zsB[nt], o);
            }
        }
        float s = 0.f, sq = 0.f;
#pragma unroll
        for (int nt = 0; nt < 8; nt++) {
            s += zsA[nt] + zsB[nt];
            sq += zsA[nt] * zsA[nt] + zsB[nt] * zsB[nt];
        }
        s  += __shfl_xor_sync(0xffffffffu, s, 1);
        s  += __shfl_xor_sync(0xffffffffu, s, 2);
        sq += __shfl_xor_sync(0xffffffffu, sq, 1);
        sq += __shfl_xor_sync(0xffffffffu, sq, 2);

        float mean = s * (1.0f / 64.0f);
        float var  = sq * (1.0f / 64.0f) - mean * mean;
        float inv  = rsqrtf(var + LN_EPS);

        if (lane < 4) {
            float* op = out + ((size_t)pair * 2 + p) * ND;
#pragma unroll
            for (int nt = 0; nt < 8; nt++) {
                int d = nt * 8 + 2 * t;
                float2 ga = *(const float2*)&gamma_[d];
                float2 be = *(const float2*)&beta_[d];
                float2 o2;
                o2.x = (zsA[nt] - mean) * inv * ga.x + be.x;
                o2.y = (zsB[nt] - mean) * inv * ga.y + be.y;
                *(float2*)&op[d] = o2;
            }
        }
    }
}

// ---------------------------------------------------------------------------
// Launch
// ---------------------------------------------------------------------------
extern "C" void kernel_launch(void* const* d_in, const int* in_sizes, int n_in,
                              void* d_out, int out_size) {
    const float* vol     = (const float*)d_in[0];
    const float* z_embed = (const float*)d_in[1];
    const float* w1      = (const float*)d_in[2];
    const float* b1      = (const float*)d_in[3];
    const float* gamma_  = (const float*)d_in[4];
    const float* beta_   = (const float*)d_in[5];
    float* out = (float*)d_out;

    prep_kernel<<<32, 256>>>(z_embed, w1, b1);
    bev_hmma<<<NPAIR / 4, 128>>>(vol, gamma_, beta_, out);
}